// round 1
// baseline (speedup 1.0000x reference)
#include <cuda_runtime.h>
#include <cuda_bf16.h>
#include <stdint.h>

// Problem dims
#define S_LEN 512
#define BATCH 64
#define DIM   1024
#define HID   1024
#define NG    4096   // 4*HID gate rows

// ---------------- device global scratch (no cudaMalloc allowed) ----------------
__device__ __nv_bfloat16 g_in_hi[(size_t)BATCH * S_LEN * DIM];
__device__ __nv_bfloat16 g_in_lo[(size_t)BATCH * S_LEN * DIM];
__device__ __nv_bfloat16 g_wx_hi[(size_t)NG * DIM];
__device__ __nv_bfloat16 g_wx_lo[(size_t)NG * DIM];
__device__ __nv_bfloat16 g_wh_hi[(size_t)NG * HID];
__device__ __nv_bfloat16 g_wh_lo[(size_t)NG * HID];
__device__ float         g_xp[(size_t)S_LEN * NG * BATCH];   // x-projection [s][n][b]
__device__ float         g_c[BATCH * HID];
__device__ __nv_bfloat16 g_h_hi[2][BATCH * HID];             // double buffered across steps
__device__ __nv_bfloat16 g_h_lo[2][BATCH * HID];

// ---------------- helpers ----------------
__device__ __forceinline__ void mma16816(float* c, const uint32_t* a, const uint32_t* b) {
    asm volatile(
        "mma.sync.aligned.m16n8k16.row.col.f32.bf16.bf16.f32 "
        "{%0,%1,%2,%3}, {%4,%5,%6,%7}, {%8,%9}, {%0,%1,%2,%3};\n"
        : "+f"(c[0]), "+f"(c[1]), "+f"(c[2]), "+f"(c[3])
        : "r"(a[0]), "r"(a[1]), "r"(a[2]), "r"(a[3]), "r"(b[0]), "r"(b[1]));
}

// fp32 -> bf16 hi + bf16 lo split
__global__ void split_kernel(const float* __restrict__ src,
                             __nv_bfloat16* __restrict__ hi,
                             __nv_bfloat16* __restrict__ lo, size_t n) {
    size_t i = (size_t)blockIdx.x * blockDim.x + threadIdx.x;
    if (i < n) {
        float v = src[i];
        __nv_bfloat16 h = __float2bfloat16_rn(v);
        hi[i] = h;
        lo[i] = __float2bfloat16_rn(v - __bfloat162float(h));
    }
}

__global__ void init_kernel() {
    int i = blockIdx.x * blockDim.x + threadIdx.x;
    if (i < BATCH * HID) {
        g_c[i] = 0.f;
        __nv_bfloat16 z = __float2bfloat16_rn(0.f);
        g_h_hi[0][i] = z; g_h_lo[0][i] = z;
        g_h_hi[1][i] = z; g_h_lo[1][i] = z;
    }
}

// ---------------- x-projection GEMM ----------------
// C[s][n][b] = sum_d Wx[n][d] * input[b][s][d]   (split-bf16, 3 terms)
// Block: 128 n-rows x 64 b (all of batch). Grid: (NG/128, S_LEN). 256 threads, 8 warps.
// Warp tile 32n x 32b = 2 m-tiles x 4 b-tiles of m16n8k16.
__global__ void __launch_bounds__(256) xproj_kernel() {
    __shared__ __align__(16) __nv_bfloat16 Ah[128][16], Al[128][16];
    __shared__ __align__(16) __nv_bfloat16 Bh[64][16],  Bl[64][16];

    const int s  = blockIdx.y;
    const int n0 = blockIdx.x * 128;
    const int t  = threadIdx.x;
    const int w  = t >> 5, l = t & 31;
    const int wm = (w & 3) * 32;   // n offset of this warp
    const int wb = (w >> 2) * 32;  // b offset of this warp

    float acc[2][4][4];
#pragma unroll
    for (int i = 0; i < 2; i++)
#pragma unroll
        for (int j = 0; j < 4; j++)
#pragma unroll
            for (int k = 0; k < 4; k++) acc[i][j][k] = 0.f;

    const int arow = t >> 1, ahalf = (t & 1) * 8;      // A: 128 rows x 16, one uint4/thread
    const int brow = t >> 2, bq = (t & 3) * 4;         // B: 64 rows x 16, one uint2/thread
    const size_t a_gbase = (size_t)(n0 + arow) * DIM + ahalf;
    const size_t b_gbase = ((size_t)brow * S_LEN + s) * DIM + bq;

    const int qr = l >> 2, tg = l & 3;                 // fragment quad-row / tid-in-group

    for (int k0 = 0; k0 < DIM; k0 += 16) {
        *(uint4*)&Ah[arow][ahalf] = *(const uint4*)&g_wx_hi[a_gbase + k0];
        *(uint4*)&Al[arow][ahalf] = *(const uint4*)&g_wx_lo[a_gbase + k0];
        *(uint2*)&Bh[brow][bq]    = *(const uint2*)&g_in_hi[b_gbase + k0];
        *(uint2*)&Bl[brow][bq]    = *(const uint2*)&g_in_lo[b_gbase + k0];
        __syncthreads();

        const uint32_t* Ah32 = (const uint32_t*)Ah;
        const uint32_t* Al32 = (const uint32_t*)Al;
        const uint32_t* Bh32 = (const uint32_t*)Bh;
        const uint32_t* Bl32 = (const uint32_t*)Bl;

        uint32_t bh[4][2], bl[4][2];
#pragma unroll
        for (int bt = 0; bt < 4; bt++) {
            int off = (wb + bt * 8 + qr) * 8 + tg;  // row stride = 8 u32
            bh[bt][0] = Bh32[off];     bh[bt][1] = Bh32[off + 4];
            bl[bt][0] = Bl32[off];     bl[bt][1] = Bl32[off + 4];
        }
#pragma unroll
        for (int mt = 0; mt < 2; mt++) {
            int ro = (wm + mt * 16 + qr) * 8 + tg;
            uint32_t ah[4], al[4];
            ah[0] = Ah32[ro];      ah[1] = Ah32[ro + 64];
            ah[2] = Ah32[ro + 4];  ah[3] = Ah32[ro + 68];
            al[0] = Al32[ro];      al[1] = Al32[ro + 64];
            al[2] = Al32[ro + 4];  al[3] = Al32[ro + 68];
#pragma unroll
            for (int bt = 0; bt < 4; bt++) {
                mma16816(acc[mt][bt], ah, bh[bt]);
                mma16816(acc[mt][bt], ah, bl[bt]);
                mma16816(acc[mt][bt], al, bh[bt]);
            }
        }
        __syncthreads();
    }

#pragma unroll
    for (int mt = 0; mt < 2; mt++) {
#pragma unroll
        for (int bt = 0; bt < 4; bt++) {
            int n = n0 + wm + mt * 16 + qr;
            int b = wb + bt * 8 + tg * 2;
            size_t base = ((size_t)s * NG + n) * BATCH + b;
            *(float2*)&g_xp[base]             = make_float2(acc[mt][bt][0], acc[mt][bt][1]);
            *(float2*)&g_xp[base + 8 * BATCH] = make_float2(acc[mt][bt][2], acc[mt][bt][3]);
        }
    }
}

// ---------------- one recurrence step (fused GEMM + gates) ----------------
// Block: 32 rows (4 gates x 8 h) x 64 b. Grid: 128 blocks (h tiles of 8).
// g = xp[s] + Wh . h_prev + bias ; gates; update c, h; write out[:, s, :].
__global__ void __launch_bounds__(256) step_kernel(int s, const float* __restrict__ bias,
                                                   float* __restrict__ out) {
    __shared__ __align__(16) __nv_bfloat16 Ah[32][16], Al[32][16];
    __shared__ __align__(16) __nv_bfloat16 Bh[64][16], Bl[64][16];
    __shared__ float gbuf[32][66];

    const int h0 = blockIdx.x * 8;
    const int t  = threadIdx.x;
    const int w  = t >> 5, l = t & 31;
    const int wm = (w & 1) * 16;   // row offset (of 32)
    const int wb = (w >> 1) * 16;  // b offset (of 64)
    const int p  = s & 1;          // h double-buffer parity

    float acc[2][4];
#pragma unroll
    for (int i = 0; i < 2; i++)
#pragma unroll
        for (int j = 0; j < 4; j++) acc[i][j] = 0.f;

    const int brow = t >> 2, bq = (t & 3) * 4;
    const int qr = l >> 2, tg = l & 3;

    for (int k0 = 0; k0 < HID; k0 += 16) {
        if (t < 128) {
            int tt = t & 63;
            int row = tt >> 1, half = (tt & 1) * 8;      // row 0..31
            int grow = (row >> 3) * HID + h0 + (row & 7); // gate*H + h
            size_t gidx = (size_t)grow * HID + k0 + half;
            if (t < 64) *(uint4*)&Ah[row][half] = *(const uint4*)&g_wh_hi[gidx];
            else        *(uint4*)&Al[row][half] = *(const uint4*)&g_wh_lo[gidx];
        }
        {
            size_t hb = (size_t)brow * HID + k0 + bq;
            *(uint2*)&Bh[brow][bq] = *(const uint2*)&g_h_hi[p][hb];
            *(uint2*)&Bl[brow][bq] = *(const uint2*)&g_h_lo[p][hb];
        }
        __syncthreads();

        const uint32_t* Ah32 = (const uint32_t*)Ah;
        const uint32_t* Al32 = (const uint32_t*)Al;
        const uint32_t* Bh32 = (const uint32_t*)Bh;
        const uint32_t* Bl32 = (const uint32_t*)Bl;

        int ro = (wm + qr) * 8 + tg;
        uint32_t ah[4], al[4];
        ah[0] = Ah32[ro];      ah[1] = Ah32[ro + 64];
        ah[2] = Ah32[ro + 4];  ah[3] = Ah32[ro + 68];
        al[0] = Al32[ro];      al[1] = Al32[ro + 64];
        al[2] = Al32[ro + 4];  al[3] = Al32[ro + 68];
#pragma unroll
        for (int bt = 0; bt < 2; bt++) {
            int off = (wb + bt * 8 + qr) * 8 + tg;
            uint32_t bhf[2] = { Bh32[off], Bh32[off + 4] };
            uint32_t blf[2] = { Bl32[off], Bl32[off + 4] };
            mma16816(acc[bt], ah, bhf);
            mma16816(acc[bt], ah, blf);
            mma16816(acc[bt], al, bhf);
        }
        __syncthreads();
    }

    // scatter gate pre-activations to smem for cross-gate pointwise
#pragma unroll
    for (int bt = 0; bt < 2; bt++) {
        int r = wm + qr;
        int b = wb + bt * 8 + tg * 2;
        gbuf[r][b]         = acc[bt][0];
        gbuf[r][b + 1]     = acc[bt][1];
        gbuf[r + 8][b]     = acc[bt][2];
        gbuf[r + 8][b + 1] = acc[bt][3];
    }
    __syncthreads();

    // pointwise: 512 cells (8 h x 64 b); h-fast mapping for coalesced out/h/c
    const size_t xpb = (size_t)s * NG * BATCH;
    for (int cell = t; cell < 512; cell += 256) {
        int hh = cell & 7, bb = cell >> 3;
        int h = h0 + hh;
        float gi = gbuf[hh][bb]      + g_xp[xpb + (size_t)(0 * HID + h) * BATCH + bb] + bias[0 * HID + h];
        float gf = gbuf[8 + hh][bb]  + g_xp[xpb + (size_t)(1 * HID + h) * BATCH + bb] + bias[1 * HID + h];
        float go = gbuf[16 + hh][bb] + g_xp[xpb + (size_t)(2 * HID + h) * BATCH + bb] + bias[2 * HID + h];
        float gc = gbuf[24 + hh][bb] + g_xp[xpb + (size_t)(3 * HID + h) * BATCH + bb] + bias[3 * HID + h];

        float i_t = 1.f / (1.f + expf(-gi));
        float f_t = 1.f / (1.f + expf(-gf));
        float o_t = 1.f / (1.f + expf(-go));
        float ch  = tanhf(gc);

        int ci = bb * HID + h;
        float cn = f_t * g_c[ci] + i_t * ch;
        float hn = o_t * tanhf(cn);
        g_c[ci] = cn;

        __nv_bfloat16 hhi = __float2bfloat16_rn(hn);
        g_h_hi[p ^ 1][ci] = hhi;
        g_h_lo[p ^ 1][ci] = __float2bfloat16_rn(hn - __bfloat162float(hhi));

        out[((size_t)bb * S_LEN + s) * HID + h] = hn;
    }
}

// ---------------- finalize: h_last (from out row s=511) + c_last ----------------
__global__ void finalize_kernel(float* __restrict__ out) {
    int i = blockIdx.x * blockDim.x + threadIdx.x;
    if (i < BATCH * HID) {
        int b = i / HID, h = i % HID;
        const size_t OUT0 = (size_t)BATCH * S_LEN * HID;
        out[OUT0 + i]               = out[((size_t)b * S_LEN + (S_LEN - 1)) * HID + h];
        out[OUT0 + BATCH * HID + i] = g_c[i];
    }
}

// ---------------- launch ----------------
extern "C" void kernel_launch(void* const* d_in, const int* in_sizes, int n_in,
                              void* d_out, int out_size) {
    const float* inp  = (const float*)d_in[0];
    const float* Wx   = (const float*)d_in[1];
    const float* Wh   = (const float*)d_in[2];
    const float* bias = (const float*)d_in[3];
    float* out = (float*)d_out;

    void *p_in_hi, *p_in_lo, *p_wx_hi, *p_wx_lo, *p_wh_hi, *p_wh_lo;
    cudaGetSymbolAddress(&p_in_hi, g_in_hi);
    cudaGetSymbolAddress(&p_in_lo, g_in_lo);
    cudaGetSymbolAddress(&p_wx_hi, g_wx_hi);
    cudaGetSymbolAddress(&p_wx_lo, g_wx_lo);
    cudaGetSymbolAddress(&p_wh_hi, g_wh_hi);
    cudaGetSymbolAddress(&p_wh_lo, g_wh_lo);

    const size_t n_inp = (size_t)BATCH * S_LEN * DIM;
    const size_t n_w   = (size_t)NG * DIM;

    split_kernel<<<(unsigned)((n_inp + 255) / 256), 256>>>(
        inp, (__nv_bfloat16*)p_in_hi, (__nv_bfloat16*)p_in_lo, n_inp);
    split_kernel<<<(unsigned)((n_w + 255) / 256), 256>>>(
        Wx, (__nv_bfloat16*)p_wx_hi, (__nv_bfloat16*)p_wx_lo, n_w);
    split_kernel<<<(unsigned)((n_w + 255) / 256), 256>>>(
        Wh, (__nv_bfloat16*)p_wh_hi, (__nv_bfloat16*)p_wh_lo, n_w);
    init_kernel<<<(BATCH * HID + 255) / 256, 256>>>();

    dim3 xg(NG / 128, S_LEN);
    xproj_kernel<<<xg, 256>>>();

    for (int s = 0; s < S_LEN; s++)
        step_kernel<<<128, 256>>>(s, bias, out);

    if ((size_t)out_size >= (size_t)BATCH * S_LEN * HID + 2 * BATCH * HID)
        finalize_kernel<<<(BATCH * HID + 255) / 256, 256>>>(out);
}

// round 2
// speedup vs baseline: 2.9073x; 2.9073x over previous
#include <cuda_runtime.h>
#include <cuda_bf16.h>
#include <stdint.h>

// Problem dims
#define S_LEN 512
#define BATCH 64
#define DIM   1024
#define HID   1024
#define NG    4096   // 4*HID gate rows
#define NBLK  128    // persistent blocks (<=148 SMs -> all co-resident)

#define A_ST  1032   // Wh smem row stride (bf16), padded for bank-conflict-free ldmatrix
#define B_ST  136    // h-chunk smem row stride (bf16), padded

// smem layout (bytes)
#define OFF_AL 66048           // 32*A_ST*2
#define OFF_BH 132096          // 2*66048
#define OFF_BL 149504          // OFF_BH + 64*B_ST*2
#define SMEM_TOT 166912        // OFF_BL + 17408

// ---------------- device global scratch (no cudaMalloc allowed) ----------------
__device__ __nv_bfloat16 g_in_hi[(size_t)BATCH * S_LEN * DIM];
__device__ __nv_bfloat16 g_in_lo[(size_t)BATCH * S_LEN * DIM];
__device__ __nv_bfloat16 g_wx_hi[(size_t)NG * DIM];
__device__ __nv_bfloat16 g_wx_lo[(size_t)NG * DIM];
__device__ __nv_bfloat16 g_wh_hi[(size_t)NG * HID];
__device__ __nv_bfloat16 g_wh_lo[(size_t)NG * HID];
__device__ float         g_xp[(size_t)S_LEN * NG * BATCH];   // x-projection [s][n][b]
__device__ float         g_c[BATCH * HID];
__device__ __nv_bfloat16 g_h_hi[2][BATCH * HID];             // double buffered across steps
__device__ __nv_bfloat16 g_h_lo[2][BATCH * HID];
__device__ unsigned      g_bar_cnt;                          // monotonic grid-barrier counter

// ---------------- helpers ----------------
__device__ __forceinline__ void mma16816(float* c, const uint32_t* a, const uint32_t* b) {
    asm volatile(
        "mma.sync.aligned.m16n8k16.row.col.f32.bf16.bf16.f32 "
        "{%0,%1,%2,%3}, {%4,%5,%6,%7}, {%8,%9}, {%0,%1,%2,%3};\n"
        : "+f"(c[0]), "+f"(c[1]), "+f"(c[2]), "+f"(c[3])
        : "r"(a[0]), "r"(a[1]), "r"(a[2]), "r"(a[3]), "r"(b[0]), "r"(b[1]));
}

__device__ __forceinline__ void ldsm4(uint32_t* r, const void* p) {
    uint32_t addr = (uint32_t)__cvta_generic_to_shared(p);
    asm volatile("ldmatrix.sync.aligned.m8n8.x4.shared.b16 {%0,%1,%2,%3}, [%4];"
                 : "=r"(r[0]), "=r"(r[1]), "=r"(r[2]), "=r"(r[3]) : "r"(addr));
}

// fp32 -> bf16 hi + bf16 lo split
__global__ void split_kernel(const float* __restrict__ src,
                             __nv_bfloat16* __restrict__ hi,
                             __nv_bfloat16* __restrict__ lo, size_t n) {
    size_t i = (size_t)blockIdx.x * blockDim.x + threadIdx.x;
    if (i < n) {
        float v = src[i];
        __nv_bfloat16 h = __float2bfloat16_rn(v);
        hi[i] = h;
        lo[i] = __float2bfloat16_rn(v - __bfloat162float(h));
    }
}

__global__ void init_kernel() {
    int i = blockIdx.x * blockDim.x + threadIdx.x;
    if (i == 0) g_bar_cnt = 0;
    if (i < BATCH * HID) {
        __nv_bfloat16 z = __float2bfloat16_rn(0.f);
        g_h_hi[0][i] = z; g_h_lo[0][i] = z;
        g_h_hi[1][i] = z; g_h_lo[1][i] = z;
    }
}

// ---------------- x-projection GEMM (unchanged, validated) ----------------
__global__ void __launch_bounds__(256) xproj_kernel() {
    __shared__ __align__(16) __nv_bfloat16 Ah[128][16], Al[128][16];
    __shared__ __align__(16) __nv_bfloat16 Bh[64][16],  Bl[64][16];

    const int s  = blockIdx.y;
    const int n0 = blockIdx.x * 128;
    const int t  = threadIdx.x;
    const int w  = t >> 5, l = t & 31;
    const int wm = (w & 3) * 32;
    const int wb = (w >> 2) * 32;

    float acc[2][4][4];
#pragma unroll
    for (int i = 0; i < 2; i++)
#pragma unroll
        for (int j = 0; j < 4; j++)
#pragma unroll
            for (int k = 0; k < 4; k++) acc[i][j][k] = 0.f;

    const int arow = t >> 1, ahalf = (t & 1) * 8;
    const int brow = t >> 2, bq = (t & 3) * 4;
    const size_t a_gbase = (size_t)(n0 + arow) * DIM + ahalf;
    const size_t b_gbase = ((size_t)brow * S_LEN + s) * DIM + bq;

    const int qr = l >> 2, tg = l & 3;

    for (int k0 = 0; k0 < DIM; k0 += 16) {
        *(uint4*)&Ah[arow][ahalf] = *(const uint4*)&g_wx_hi[a_gbase + k0];
        *(uint4*)&Al[arow][ahalf] = *(const uint4*)&g_wx_lo[a_gbase + k0];
        *(uint2*)&Bh[brow][bq]    = *(const uint2*)&g_in_hi[b_gbase + k0];
        *(uint2*)&Bl[brow][bq]    = *(const uint2*)&g_in_lo[b_gbase + k0];
        __syncthreads();

        const uint32_t* Ah32 = (const uint32_t*)Ah;
        const uint32_t* Al32 = (const uint32_t*)Al;
        const uint32_t* Bh32 = (const uint32_t*)Bh;
        const uint32_t* Bl32 = (const uint32_t*)Bl;

        uint32_t bh[4][2], bl[4][2];
#pragma unroll
        for (int bt = 0; bt < 4; bt++) {
            int off = (wb + bt * 8 + qr) * 8 + tg;
            bh[bt][0] = Bh32[off];     bh[bt][1] = Bh32[off + 4];
            bl[bt][0] = Bl32[off];     bl[bt][1] = Bl32[off + 4];
        }
#pragma unroll
        for (int mt = 0; mt < 2; mt++) {
            int ro = (wm + mt * 16 + qr) * 8 + tg;
            uint32_t ah[4], al[4];
            ah[0] = Ah32[ro];      ah[1] = Ah32[ro + 64];
            ah[2] = Ah32[ro + 4];  ah[3] = Ah32[ro + 68];
            al[0] = Al32[ro];      al[1] = Al32[ro + 64];
            al[2] = Al32[ro + 4];  al[3] = Al32[ro + 68];
#pragma unroll
            for (int bt = 0; bt < 4; bt++) {
                mma16816(acc[mt][bt], ah, bh[bt]);
                mma16816(acc[mt][bt], ah, bl[bt]);
                mma16816(acc[mt][bt], al, bh[bt]);
            }
        }
        __syncthreads();
    }

#pragma unroll
    for (int mt = 0; mt < 2; mt++) {
#pragma unroll
        for (int bt = 0; bt < 4; bt++) {
            int n = n0 + wm + mt * 16 + qr;
            int b = wb + bt * 8 + tg * 2;
            size_t base = ((size_t)s * NG + n) * BATCH + b;
            *(float2*)&g_xp[base]             = make_float2(acc[mt][bt][0], acc[mt][bt][1]);
            *(float2*)&g_xp[base + 8 * BATCH] = make_float2(acc[mt][bt][2], acc[mt][bt][3]);
        }
    }
}

// ---------------- persistent recurrence kernel ----------------
// 128 blocks x 256 threads. Block owns 32 gate-rows (8 h-values x 4 gates),
// Wh slice (hi+lo) resident in SMEM for all 512 steps. Cell state c in registers.
// Grid-wide barrier between steps; h double-buffered in global bf16 hi/lo.
__global__ void __launch_bounds__(256) lstm_rec_kernel(const float* __restrict__ bias,
                                                       float* __restrict__ out) {
    extern __shared__ __align__(16) char smem[];
    __nv_bfloat16* Ah  = (__nv_bfloat16*)(smem);
    __nv_bfloat16* Al  = (__nv_bfloat16*)(smem + OFF_AL);
    __nv_bfloat16* Bsh = (__nv_bfloat16*)(smem + OFF_BH);
    __nv_bfloat16* Bsl = (__nv_bfloat16*)(smem + OFF_BL);
    float*         gbuf = (float*)(smem + OFF_BH);   // reused after k-loop

    const int t = threadIdx.x;
    const int w = t >> 5, l = t & 31;
    const int h0 = blockIdx.x * 8;

    // ---- load resident Wh slice: 32 rows (gate*8 + hh), hi+lo ----
    for (int i = t; i < 4096; i += 256) {            // 32 rows * 128 uint4
        int r = i >> 7;
        int c = (i & 127) * 8;
        int grow = ((r >> 3) << 10) + h0 + (r & 7);  // gate*HID + h
        size_t g = (size_t)grow * HID + c;
        *(uint4*)&Ah[r * A_ST + c] = *(const uint4*)&g_wh_hi[g];
        *(uint4*)&Al[r * A_ST + c] = *(const uint4*)&g_wh_lo[g];
    }

    // per-thread pointwise mapping: cells (hh, bb) and (hh, bb+32)
    const int hh = t & 7, bb = t >> 3;
    const float bi  = bias[0 * HID + h0 + hh];
    const float bf_ = bias[1 * HID + h0 + hh];
    const float bo  = bias[2 * HID + h0 + hh];
    const float bc  = bias[3 * HID + h0 + hh];
    float c1 = 0.f, c2 = 0.f;

    // warp tile: 16 rows x 16 cols
    const int wr = (w & 1) * 16;
    const int wc = (w >> 1) * 16;
    const int qr = l >> 2, tg = l & 3;
    // ldmatrix lane source rows/cols
    const int a_row = wr + (l & 15);
    const int a_col = (l >> 4) * 8;
    const int b_row = wc + (l & 7) + ((l >> 4) << 3);
    const int b_col = ((l >> 3) & 1) * 8;

    __syncthreads();

    for (int s = 0; s < S_LEN; s++) {
        const int p = s & 1;
        const __nv_bfloat16* hsrc_hi = g_h_hi[p];
        const __nv_bfloat16* hsrc_lo = g_h_lo[p];

        float acc0[4] = {0.f, 0.f, 0.f, 0.f};
        float acc1[4] = {0.f, 0.f, 0.f, 0.f};

        for (int k0 = 0; k0 < HID; k0 += 128) {
            // stage h[0:64][k0:k0+128] hi+lo into SMEM (L1-bypassed: cross-SM producer)
            {
                int r  = t >> 2;
                int cq = (t & 3) * 8;
#pragma unroll
                for (int pass = 0; pass < 4; pass++) {
                    int c = cq + pass * 32;
                    size_t gidx = (size_t)r * HID + k0 + c;
                    *(uint4*)&Bsh[r * B_ST + c] = __ldcg((const uint4*)&hsrc_hi[gidx]);
                    *(uint4*)&Bsl[r * B_ST + c] = __ldcg((const uint4*)&hsrc_lo[gidx]);
                }
            }
            __syncthreads();
#pragma unroll
            for (int kk = 0; kk < 128; kk += 16) {
                uint32_t ah[4], al[4], bh[4], bl[4];
                ldsm4(ah, &Ah[a_row * A_ST + k0 + kk + a_col]);
                ldsm4(al, &Al[a_row * A_ST + k0 + kk + a_col]);
                ldsm4(bh, &Bsh[b_row * B_ST + kk + b_col]);
                ldsm4(bl, &Bsl[b_row * B_ST + kk + b_col]);
                mma16816(acc0, ah, &bh[0]);
                mma16816(acc0, ah, &bl[0]);
                mma16816(acc0, al, &bh[0]);
                mma16816(acc1, ah, &bh[2]);
                mma16816(acc1, ah, &bl[2]);
                mma16816(acc1, al, &bh[2]);
            }
            __syncthreads();
        }

        // scatter gate pre-activations (C frag: row wr+qr(+8), col wc(+8)+2tg)
        {
            int r0 = wr + qr, r1 = wr + qr + 8;
            int cA = wc + tg * 2, cB = wc + 8 + tg * 2;
            gbuf[r0 * 66 + cA]     = acc0[0];
            gbuf[r0 * 66 + cA + 1] = acc0[1];
            gbuf[r1 * 66 + cA]     = acc0[2];
            gbuf[r1 * 66 + cA + 1] = acc0[3];
            gbuf[r0 * 66 + cB]     = acc1[0];
            gbuf[r0 * 66 + cB + 1] = acc1[1];
            gbuf[r1 * 66 + cB]     = acc1[2];
            gbuf[r1 * 66 + cB + 1] = acc1[3];
        }
        __syncthreads();

        // pointwise: 2 cells per thread
        {
            const size_t xpb = (size_t)s * ((size_t)NG * BATCH);
            const int h = h0 + hh;
#pragma unroll
            for (int cc = 0; cc < 2; cc++) {
                int b = bb + cc * 32;
                float gi = gbuf[(0 * 8 + hh) * 66 + b] + __ldg(&g_xp[xpb + (size_t)(0 * HID + h) * BATCH + b]) + bi;
                float gf = gbuf[(1 * 8 + hh) * 66 + b] + __ldg(&g_xp[xpb + (size_t)(1 * HID + h) * BATCH + b]) + bf_;
                float go = gbuf[(2 * 8 + hh) * 66 + b] + __ldg(&g_xp[xpb + (size_t)(2 * HID + h) * BATCH + b]) + bo;
                float gc = gbuf[(3 * 8 + hh) * 66 + b] + __ldg(&g_xp[xpb + (size_t)(3 * HID + h) * BATCH + b]) + bc;

                float it = 1.f / (1.f + expf(-gi));
                float ft = 1.f / (1.f + expf(-gf));
                float ot = 1.f / (1.f + expf(-go));
                float ch = tanhf(gc);

                float cprev = cc ? c2 : c1;
                float cn = ft * cprev + it * ch;
                float hn = ot * tanhf(cn);
                if (cc) c2 = cn; else c1 = cn;

                int ci = b * HID + h;
                __nv_bfloat16 hhi = __float2bfloat16_rn(hn);
                g_h_hi[p ^ 1][ci] = hhi;
                g_h_lo[p ^ 1][ci] = __float2bfloat16_rn(hn - __bfloat162float(hhi));
                out[((size_t)b * S_LEN + s) * HID + h] = hn;
                if (s == S_LEN - 1) g_c[ci] = cn;
            }
        }

        // grid barrier (skip after last step)
        if (s < S_LEN - 1) {
            __syncthreads();
            if (t == 0) {
                __threadfence();
                unsigned my = atomicAdd(&g_bar_cnt, 1u) + 1u;
                unsigned need = ((my + NBLK - 1u) / NBLK) * NBLK;
                unsigned cur;
                do {
                    asm volatile("ld.acquire.gpu.u32 %0, [%1];"
                                 : "=r"(cur) : "l"(&g_bar_cnt));
                } while (cur < need);
            }
            __syncthreads();
        }
    }
}

// ---------------- finalize: h_last (from out row s=511) + c_last ----------------
__global__ void finalize_kernel(float* __restrict__ out) {
    int i = blockIdx.x * blockDim.x + threadIdx.x;
    if (i < BATCH * HID) {
        int b = i / HID, h = i % HID;
        const size_t OUT0 = (size_t)BATCH * S_LEN * HID;
        out[OUT0 + i]               = out[((size_t)b * S_LEN + (S_LEN - 1)) * HID + h];
        out[OUT0 + BATCH * HID + i] = g_c[i];
    }
}

// ---------------- launch ----------------
extern "C" void kernel_launch(void* const* d_in, const int* in_sizes, int n_in,
                              void* d_out, int out_size) {
    const float* inp  = (const float*)d_in[0];
    const float* Wx   = (const float*)d_in[1];
    const float* Wh   = (const float*)d_in[2];
    const float* bias = (const float*)d_in[3];
    float* out = (float*)d_out;

    void *p_in_hi, *p_in_lo, *p_wx_hi, *p_wx_lo, *p_wh_hi, *p_wh_lo;
    cudaGetSymbolAddress(&p_in_hi, g_in_hi);
    cudaGetSymbolAddress(&p_in_lo, g_in_lo);
    cudaGetSymbolAddress(&p_wx_hi, g_wx_hi);
    cudaGetSymbolAddress(&p_wx_lo, g_wx_lo);
    cudaGetSymbolAddress(&p_wh_hi, g_wh_hi);
    cudaGetSymbolAddress(&p_wh_lo, g_wh_lo);

    static int smem_configured = 0;
    if (!smem_configured) {
        cudaFuncSetAttribute(lstm_rec_kernel,
                             cudaFuncAttributeMaxDynamicSharedMemorySize, SMEM_TOT);
        smem_configured = 1;
    }

    const size_t n_inp = (size_t)BATCH * S_LEN * DIM;
    const size_t n_w   = (size_t)NG * DIM;

    split_kernel<<<(unsigned)((n_inp + 255) / 256), 256>>>(
        inp, (__nv_bfloat16*)p_in_hi, (__nv_bfloat16*)p_in_lo, n_inp);
    split_kernel<<<(unsigned)((n_w + 255) / 256), 256>>>(
        Wx, (__nv_bfloat16*)p_wx_hi, (__nv_bfloat16*)p_wx_lo, n_w);
    split_kernel<<<(unsigned)((n_w + 255) / 256), 256>>>(
        Wh, (__nv_bfloat16*)p_wh_hi, (__nv_bfloat16*)p_wh_lo, n_w);
    init_kernel<<<(BATCH * HID + 255) / 256, 256>>>();

    dim3 xg(NG / 128, S_LEN);
    xproj_kernel<<<xg, 256>>>();

    lstm_rec_kernel<<<NBLK, 256, SMEM_TOT>>>(bias, out);

    if ((size_t)out_size >= (size_t)BATCH * S_LEN * HID + 2 * BATCH * HID)
        finalize_kernel<<<(BATCH * HID + 255) / 256, 256>>>(out);
}

// round 3
// speedup vs baseline: 3.1697x; 1.0903x over previous
#include <cuda_runtime.h>
#include <cuda_bf16.h>
#include <stdint.h>

// Problem dims
#define S_LEN 512
#define BATCH 64
#define DIM   1024
#define HID   1024
#define NG    4096   // 4*HID gate rows
#define NBLK  128    // persistent blocks (<=148 SMs -> all co-resident)

#define A_ST  1032   // Wh smem row stride (bf16): 4-bank row step, ldmatrix conflict-free
#define B_ST  136    // h-chunk smem row stride (bf16)

// recurrence smem layout (bytes)
#define OFF_AL  66048           // 32*A_ST*2
#define OFF_B0H 132096
#define OFF_B0L 149504          // +64*B_ST*2
#define OFF_B1H 166912
#define OFF_B1L 184320
#define SMEM_REC 201728

// xproj smem: 2 buffers x 20480 bf16 (Ah 0 / Al 5120 / Bh 10240 / Bl 15360), stride 40
#define XA_ST 40
#define XBUF_ELEMS 20480
#define SMEM_XP (2 * XBUF_ELEMS * 2)

// ---------------- device global scratch ----------------
__device__ __nv_bfloat16 g_in_hi[(size_t)BATCH * S_LEN * DIM];
__device__ __nv_bfloat16 g_in_lo[(size_t)BATCH * S_LEN * DIM];
__device__ __nv_bfloat16 g_wx_hi[(size_t)NG * DIM];
__device__ __nv_bfloat16 g_wx_lo[(size_t)NG * DIM];
__device__ __nv_bfloat16 g_wh_hi[(size_t)NG * HID];
__device__ __nv_bfloat16 g_wh_lo[(size_t)NG * HID];
__device__ float         g_xp[(size_t)S_LEN * NG * BATCH];   // [s][n][b]
__device__ float         g_c[BATCH * HID];
__device__ __nv_bfloat16 g_h_hi[2][BATCH * HID];
__device__ __nv_bfloat16 g_h_lo[2][BATCH * HID];
__device__ unsigned      g_bar_cnt;

// ---------------- helpers ----------------
__device__ __forceinline__ void mma16816(float* c, const uint32_t* a, const uint32_t* b) {
    asm volatile(
        "mma.sync.aligned.m16n8k16.row.col.f32.bf16.bf16.f32 "
        "{%0,%1,%2,%3}, {%4,%5,%6,%7}, {%8,%9}, {%0,%1,%2,%3};\n"
        : "+f"(c[0]), "+f"(c[1]), "+f"(c[2]), "+f"(c[3])
        : "r"(a[0]), "r"(a[1]), "r"(a[2]), "r"(a[3]), "r"(b[0]), "r"(b[1]));
}

__device__ __forceinline__ void ldsm4(uint32_t* r, const void* p) {
    uint32_t addr = (uint32_t)__cvta_generic_to_shared(p);
    asm volatile("ldmatrix.sync.aligned.m8n8.x4.shared.b16 {%0,%1,%2,%3}, [%4];"
                 : "=r"(r[0]), "=r"(r[1]), "=r"(r[2]), "=r"(r[3]) : "r"(addr));
}

__device__ __forceinline__ uint32_t smem_u32(const void* p) {
    return (uint32_t)__cvta_generic_to_shared(p);
}
#define CPA(dst, src) asm volatile("cp.async.cg.shared.global [%0], [%1], 16;\n" :: "r"(dst), "l"(src))
#define CP_COMMIT()   asm volatile("cp.async.commit_group;\n")
#define CP_WAIT(n)    asm volatile("cp.async.wait_group %0;\n" :: "n"(n))

// fp32 -> bf16 hi + bf16 lo split
__global__ void split_kernel(const float* __restrict__ src,
                             __nv_bfloat16* __restrict__ hi,
                             __nv_bfloat16* __restrict__ lo, size_t n) {
    size_t i = (size_t)blockIdx.x * blockDim.x + threadIdx.x;
    if (i < n) {
        float v = src[i];
        __nv_bfloat16 h = __float2bfloat16_rn(v);
        hi[i] = h;
        lo[i] = __float2bfloat16_rn(v - __bfloat162float(h));
    }
}

__global__ void init_kernel() {
    int i = blockIdx.x * blockDim.x + threadIdx.x;
    if (i == 0) g_bar_cnt = 0;
    if (i < BATCH * HID) {
        __nv_bfloat16 z = __float2bfloat16_rn(0.f);
        g_h_hi[0][i] = z; g_h_lo[0][i] = z;
        g_h_hi[1][i] = z; g_h_lo[1][i] = z;
    }
}

// ---------------- x-projection GEMM ----------------
// C[n][c] over block tile 128n x 128c, c = s_local*64 + b (2 seq positions / block).
// K-chunk 32, double-buffered cp.async.cg, 8 warps (4n x 2c), warp tile 32n x 64c.
__global__ void __launch_bounds__(256, 2) xproj_kernel() {
    extern __shared__ __align__(16) __nv_bfloat16 xs[];

    const int s0 = blockIdx.y * 2;
    const int n0 = blockIdx.x * 128;
    const int t  = threadIdx.x;
    const int w  = t >> 5, l = t & 31;
    const int wm = (w & 3) * 32;    // warp n offset
    const int wc = (w >> 2) * 64;   // warp c offset

    float acc[2][8][4];
#pragma unroll
    for (int i = 0; i < 2; i++)
#pragma unroll
        for (int j = 0; j < 8; j++)
#pragma unroll
            for (int k = 0; k < 4; k++) acc[i][j][k] = 0.f;

    const int lr  = t >> 2;          // load row (0..63), +64 for second pass
    const int lcq = (t & 3) * 8;     // load col (uint4 within 32-wide chunk)
    const int qr = l >> 2, tg = l & 3;
    const int a_col = (l >> 4) * 8;
    const int b_col = ((l >> 3) & 1) * 8;

    // stage chunk k0 into buffer `bs`
    auto stage = [&](int k0, int bs) {
        __nv_bfloat16* base = xs + bs * XBUF_ELEMS;
#pragma unroll
        for (int j = 0; j < 2; j++) {
            int r = lr + j * 64;
            size_t ga = (size_t)(n0 + r) * DIM + k0 + lcq;
            CPA(smem_u32(base + r * XA_ST + lcq),        g_wx_hi + ga);
            CPA(smem_u32(base + 5120 + r * XA_ST + lcq), g_wx_lo + ga);
            int b = r & 63, sl = r >> 6;
            size_t gb = ((size_t)b * S_LEN + s0 + sl) * DIM + k0 + lcq;
            CPA(smem_u32(base + 10240 + r * XA_ST + lcq), g_in_hi + gb);
            CPA(smem_u32(base + 15360 + r * XA_ST + lcq), g_in_lo + gb);
        }
    };

    stage(0, 0);
    CP_COMMIT();

    const int NCH = DIM / 32;
    for (int c = 0; c < NCH; c++) {
        if (c + 1 < NCH) {
            stage((c + 1) * 32, (c + 1) & 1);
            CP_COMMIT();
            CP_WAIT(1);
        } else {
            CP_WAIT(0);
        }
        __syncthreads();

        const __nv_bfloat16* base = xs + (c & 1) * XBUF_ELEMS;
#pragma unroll
        for (int kk = 0; kk < 32; kk += 16) {
            uint32_t ah[2][4], al[2][4];
#pragma unroll
            for (int mt = 0; mt < 2; mt++) {
                int a_row = wm + mt * 16 + (l & 15);
                ldsm4(ah[mt], base + a_row * XA_ST + kk + a_col);
                ldsm4(al[mt], base + 5120 + a_row * XA_ST + kk + a_col);
            }
#pragma unroll
            for (int bg = 0; bg < 4; bg++) {
                int b_row = wc + bg * 16 + (l & 7) + ((l >> 4) << 3);
                uint32_t bh[4], bl[4];
                ldsm4(bh, base + 10240 + b_row * XA_ST + kk + b_col);
                ldsm4(bl, base + 15360 + b_row * XA_ST + kk + b_col);
                float* a00 = acc[0][2 * bg];
                float* a01 = acc[0][2 * bg + 1];
                float* a10 = acc[1][2 * bg];
                float* a11 = acc[1][2 * bg + 1];
                mma16816(a00, ah[0], &bh[0]); mma16816(a10, ah[1], &bh[0]);
                mma16816(a01, ah[0], &bh[2]); mma16816(a11, ah[1], &bh[2]);
                mma16816(a00, ah[0], &bl[0]); mma16816(a10, ah[1], &bl[0]);
                mma16816(a01, ah[0], &bl[2]); mma16816(a11, ah[1], &bl[2]);
                mma16816(a00, al[0], &bh[0]); mma16816(a10, al[1], &bh[0]);
                mma16816(a01, al[0], &bh[2]); mma16816(a11, al[1], &bh[2]);
            }
        }
        __syncthreads();
    }

    // epilogue: C[n][c] -> g_xp[s][n][b]
#pragma unroll
    for (int mt = 0; mt < 2; mt++) {
#pragma unroll
        for (int bg = 0; bg < 4; bg++) {
#pragma unroll
            for (int half = 0; half < 2; half++) {
                const float* a = acc[mt][2 * bg + half];
                int n = n0 + wm + mt * 16 + qr;
                int cc = wc + bg * 16 + half * 8 + tg * 2;
                int s = s0 + (cc >> 6);
                int b = cc & 63;
                size_t base = ((size_t)s * NG + n) * BATCH + b;
                *(float2*)&g_xp[base]             = make_float2(a[0], a[1]);
                *(float2*)&g_xp[base + 8 * BATCH] = make_float2(a[2], a[3]);
            }
        }
    }
}

// ---------------- persistent recurrence kernel ----------------
__global__ void __launch_bounds__(256) lstm_rec_kernel(const float* __restrict__ bias,
                                                       float* __restrict__ out) {
    extern __shared__ __align__(16) char smem[];
    __nv_bfloat16* Ah = (__nv_bfloat16*)(smem);
    __nv_bfloat16* Al = (__nv_bfloat16*)(smem + OFF_AL);
    __nv_bfloat16* BufH[2] = { (__nv_bfloat16*)(smem + OFF_B0H), (__nv_bfloat16*)(smem + OFF_B1H) };
    __nv_bfloat16* BufL[2] = { (__nv_bfloat16*)(smem + OFF_B0L), (__nv_bfloat16*)(smem + OFF_B1L) };
    float* gbuf = (float*)(smem + OFF_B0H);   // overlays buffer 0 after k-loop drains

    const int t = threadIdx.x;
    const int w = t >> 5, l = t & 31;
    const int h0 = blockIdx.x * 8;

    // resident Wh slice: 32 rows (gate*8 + hh) x 1024, hi+lo
    for (int i = t; i < 4096; i += 256) {
        int r = i >> 7;
        int c = (i & 127) * 8;
        int grow = ((r >> 3) << 10) + h0 + (r & 7);
        size_t g = (size_t)grow * HID + c;
        *(uint4*)&Ah[r * A_ST + c] = *(const uint4*)&g_wh_hi[g];
        *(uint4*)&Al[r * A_ST + c] = *(const uint4*)&g_wh_lo[g];
    }

    const int hh = t & 7, bb = t >> 3;
    const float bi  = bias[0 * HID + h0 + hh];
    const float bf_ = bias[1 * HID + h0 + hh];
    const float bo  = bias[2 * HID + h0 + hh];
    const float bc  = bias[3 * HID + h0 + hh];
    float c1 = 0.f, c2 = 0.f;

    const int wr = (w & 1) * 16;
    const int wc = (w >> 1) * 16;
    const int qr = l >> 2, tg = l & 3;
    const int a_row = wr + (l & 15);
    const int a_col = (l >> 4) * 8;
    const int b_row = wc + (l & 7) + ((l >> 4) << 3);
    const int b_col = ((l >> 3) & 1) * 8;

    const int sr = t >> 4, scq = (t & 15) * 8;   // stage: rows step 16/iter

    __syncthreads();

    for (int s = 0; s < S_LEN; s++) {
        const int p = s & 1;
        const __nv_bfloat16* hsrc_hi = g_h_hi[p];
        const __nv_bfloat16* hsrc_lo = g_h_lo[p];

        float acc0[4] = {0.f, 0.f, 0.f, 0.f};
        float acc1[4] = {0.f, 0.f, 0.f, 0.f};

        // stage chunk k0 (64 rows x 128 cols, hi+lo) into buffer bs via cp.async.cg
        auto stage = [&](int k0, int bs) {
#pragma unroll
            for (int j = 0; j < 4; j++) {
                int r = sr + j * 16;
                size_t g = (size_t)r * HID + k0 + scq;
                CPA(smem_u32(BufH[bs] + r * B_ST + scq), hsrc_hi + g);
                CPA(smem_u32(BufL[bs] + r * B_ST + scq), hsrc_lo + g);
            }
        };

        stage(0, 0);
        CP_COMMIT();

        for (int c = 0; c < 8; c++) {
            if (c < 7) {
                stage((c + 1) * 128, (c + 1) & 1);
                CP_COMMIT();
                CP_WAIT(1);
            } else {
                CP_WAIT(0);
            }
            __syncthreads();

            const __nv_bfloat16* Bh = BufH[c & 1];
            const __nv_bfloat16* Bl = BufL[c & 1];
            const int k0 = c * 128;
#pragma unroll
            for (int kk = 0; kk < 128; kk += 16) {
                uint32_t ah[4], al[4], bh[4], bl[4];
                ldsm4(ah, &Ah[a_row * A_ST + k0 + kk + a_col]);
                ldsm4(al, &Al[a_row * A_ST + k0 + kk + a_col]);
                ldsm4(bh, &Bh[b_row * B_ST + kk + b_col]);
                ldsm4(bl, &Bl[b_row * B_ST + kk + b_col]);
                mma16816(acc0, ah, &bh[0]); mma16816(acc1, ah, &bh[2]);
                mma16816(acc0, ah, &bl[0]); mma16816(acc1, ah, &bl[2]);
                mma16816(acc0, al, &bh[0]); mma16816(acc1, al, &bh[2]);
            }
            __syncthreads();
        }

        // scatter gate pre-activations
        {
            int r0 = wr + qr, r1 = wr + qr + 8;
            int cA = wc + tg * 2, cB = wc + 8 + tg * 2;
            gbuf[r0 * 66 + cA]     = acc0[0];
            gbuf[r0 * 66 + cA + 1] = acc0[1];
            gbuf[r1 * 66 + cA]     = acc0[2];
            gbuf[r1 * 66 + cA + 1] = acc0[3];
            gbuf[r0 * 66 + cB]     = acc1[0];
            gbuf[r0 * 66 + cB + 1] = acc1[1];
            gbuf[r1 * 66 + cB]     = acc1[2];
            gbuf[r1 * 66 + cB + 1] = acc1[3];
        }
        __syncthreads();

        // pointwise: 2 cells per thread
        {
            const size_t xpb = (size_t)s * ((size_t)NG * BATCH);
            const int h = h0 + hh;
#pragma unroll
            for (int cc = 0; cc < 2; cc++) {
                int b = bb + cc * 32;
                float gi = gbuf[(0 * 8 + hh) * 66 + b] + __ldg(&g_xp[xpb + (size_t)(0 * HID + h) * BATCH + b]) + bi;
                float gf = gbuf[(1 * 8 + hh) * 66 + b] + __ldg(&g_xp[xpb + (size_t)(1 * HID + h) * BATCH + b]) + bf_;
                float go = gbuf[(2 * 8 + hh) * 66 + b] + __ldg(&g_xp[xpb + (size_t)(2 * HID + h) * BATCH + b]) + bo;
                float gc = gbuf[(3 * 8 + hh) * 66 + b] + __ldg(&g_xp[xpb + (size_t)(3 * HID + h) * BATCH + b]) + bc;

                float it = 1.f / (1.f + expf(-gi));
                float ft = 1.f / (1.f + expf(-gf));
                float ot = 1.f / (1.f + expf(-go));
                float ch = tanhf(gc);

                float cprev = cc ? c2 : c1;
                float cn = ft * cprev + it * ch;
                float hn = ot * tanhf(cn);
                if (cc) c2 = cn; else c1 = cn;

                int ci = b * HID + h;
                __nv_bfloat16 hhi = __float2bfloat16_rn(hn);
                g_h_hi[p ^ 1][ci] = hhi;
                g_h_lo[p ^ 1][ci] = __float2bfloat16_rn(hn - __bfloat162float(hhi));
                out[((size_t)b * S_LEN + s) * HID + h] = hn;
                if (s == S_LEN - 1) g_c[ci] = cn;
            }
        }

        // grid barrier
        if (s < S_LEN - 1) {
            __syncthreads();
            if (t == 0) {
                __threadfence();
                unsigned my = atomicAdd(&g_bar_cnt, 1u) + 1u;
                unsigned need = ((my + NBLK - 1u) / NBLK) * NBLK;
                unsigned cur;
                do {
                    asm volatile("ld.acquire.gpu.u32 %0, [%1];"
                                 : "=r"(cur) : "l"(&g_bar_cnt));
                } while (cur < need);
            }
            __syncthreads();
        }
    }
}

// ---------------- finalize ----------------
__global__ void finalize_kernel(float* __restrict__ out) {
    int i = blockIdx.x * blockDim.x + threadIdx.x;
    if (i < BATCH * HID) {
        int b = i / HID, h = i % HID;
        const size_t OUT0 = (size_t)BATCH * S_LEN * HID;
        out[OUT0 + i]               = out[((size_t)b * S_LEN + (S_LEN - 1)) * HID + h];
        out[OUT0 + BATCH * HID + i] = g_c[i];
    }
}

// ---------------- launch ----------------
extern "C" void kernel_launch(void* const* d_in, const int* in_sizes, int n_in,
                              void* d_out, int out_size) {
    const float* inp  = (const float*)d_in[0];
    const float* Wx   = (const float*)d_in[1];
    const float* Wh   = (const float*)d_in[2];
    const float* bias = (const float*)d_in[3];
    float* out = (float*)d_out;

    void *p_in_hi, *p_in_lo, *p_wx_hi, *p_wx_lo, *p_wh_hi, *p_wh_lo;
    cudaGetSymbolAddress(&p_in_hi, g_in_hi);
    cudaGetSymbolAddress(&p_in_lo, g_in_lo);
    cudaGetSymbolAddress(&p_wx_hi, g_wx_hi);
    cudaGetSymbolAddress(&p_wx_lo, g_wx_lo);
    cudaGetSymbolAddress(&p_wh_hi, g_wh_hi);
    cudaGetSymbolAddress(&p_wh_lo, g_wh_lo);

    static int configured = 0;
    if (!configured) {
        cudaFuncSetAttribute(lstm_rec_kernel,
                             cudaFuncAttributeMaxDynamicSharedMemorySize, SMEM_REC);
        cudaFuncSetAttribute(xproj_kernel,
                             cudaFuncAttributeMaxDynamicSharedMemorySize, SMEM_XP);
        configured = 1;
    }

    const size_t n_inp = (size_t)BATCH * S_LEN * DIM;
    const size_t n_w   = (size_t)NG * DIM;

    split_kernel<<<(unsigned)((n_inp + 255) / 256), 256>>>(
        inp, (__nv_bfloat16*)p_in_hi, (__nv_bfloat16*)p_in_lo, n_inp);
    split_kernel<<<(unsigned)((n_w + 255) / 256), 256>>>(
        Wx, (__nv_bfloat16*)p_wx_hi, (__nv_bfloat16*)p_wx_lo, n_w);
    split_kernel<<<(unsigned)((n_w + 255) / 256), 256>>>(
        Wh, (__nv_bfloat16*)p_wh_hi, (__nv_bfloat16*)p_wh_lo, n_w);
    init_kernel<<<(BATCH * HID + 255) / 256, 256>>>();

    dim3 xg(NG / 128, S_LEN / 2);
    xproj_kernel<<<xg, 256, SMEM_XP>>>();

    lstm_rec_kernel<<<NBLK, 256, SMEM_REC>>>(bias, out);

    if ((size_t)out_size >= (size_t)BATCH * S_LEN * HID + 2 * BATCH * HID)
        finalize_kernel<<<(BATCH * HID + 255) / 256, 256>>>(out);
}